// round 1
// baseline (speedup 1.0000x reference)
#include <cuda_runtime.h>
#include <math.h>

// NPSLoss: mean over pixels of sqrt(min_k ||p - c_k||^2), codebook = fixed
// 20-color PRINTER_COLORS (compile-time constants -> FFMA-imm forms).
//
// d2_k = |p|^2 + (|c_k|^2 - 2 p.c_k). |p|^2 is color-independent; the min is
// taken over the affine scores s_k = |c_k|^2 - 2 p.c_k. s_0 (black) == 0.

#define HW_SHIFT 18            // 512*512 = 2^18
#define HW (1 << HW_SHIFT)

__device__ __forceinline__ float pix_dist(float r, float g, float b) {
    float rg  = r + g;
    float rb  = r + b;
    float gb  = g + b;
    float rgb = rg + b;
    float pp  = fmaf(r, r, fmaf(g, g, b * b));

    // chain A
    float ma = fmaf(-2.0f, rgb, 3.0f);              // (1,1,1)
    ma = fminf(ma, fmaf(-2.0f, r, 1.0f));           // (1,0,0)
    ma = fminf(ma, fmaf(-2.0f, g, 1.0f));           // (0,1,0)
    ma = fminf(ma, fmaf(-2.0f, b, 1.0f));           // (0,0,1)
    ma = fminf(ma, fmaf(-2.0f, rg, 2.0f));          // (1,1,0)
    ma = fminf(ma, fmaf(-2.0f, rb, 2.0f));          // (1,0,1)
    ma = fminf(ma, fmaf(-2.0f, gb, 2.0f));          // (0,1,1)
    ma = fminf(ma, 0.75f - rgb);                    // (.5,.5,.5)
    ma = fminf(ma, fmaf(-1.5f, rgb, 1.6875f));      // (.75,.75,.75)
    ma = fminf(ma, 0.0f);                           // (0,0,0)

    // chain B (independent -> ILP)
    float mb = 0.25f - r;                           // (.5,0,0)
    mb = fminf(mb, 0.25f - g);                      // (0,.5,0)
    mb = fminf(mb, 0.25f - b);                      // (0,0,.5)
    mb = fminf(mb, 0.5f - rg);                      // (.5,.5,0)
    mb = fminf(mb, 0.5f - rb);                      // (.5,0,.5)
    mb = fminf(mb, 0.5f - gb);                      // (0,.5,.5)
    mb = fminf(mb, fmaf(-0.5f, rgb, 0.1875f));      // (.25,.25,.25)
    mb = fminf(mb, fmaf(-1.5f, r, 0.5625f));        // (.75,0,0)
    mb = fminf(mb, fmaf(-1.5f, g, 0.5625f));        // (0,.75,0)
    mb = fminf(mb, fmaf(-1.5f, b, 0.5625f));        // (0,0,.75)

    float d2 = fmaxf(pp + fminf(ma, mb), 0.0f);
    return sqrtf(d2);
}

__global__ void nps_zero_kernel(float* out) {
    if (threadIdx.x == 0 && blockIdx.x == 0) out[0] = 0.0f;
}

__global__ void __launch_bounds__(256) nps_loss_kernel(
    const float* __restrict__ x, float* __restrict__ out,
    int n_groups, float inv_n)
{
    float acc = 0.0f;
    const int stride = gridDim.x * blockDim.x;
    for (int gi = blockIdx.x * blockDim.x + threadIdx.x; gi < n_groups; gi += stride) {
        int p   = gi << 2;                 // first pixel of this 4-pixel group
        int img = p >> HW_SHIFT;           // batch index
        int off = p & (HW - 1);            // pixel offset within image
        const float* base = x + (size_t)img * (3 * HW) + off;
        float4 r4 = *reinterpret_cast<const float4*>(base);
        float4 g4 = *reinterpret_cast<const float4*>(base + HW);
        float4 b4 = *reinterpret_cast<const float4*>(base + 2 * HW);
        acc += pix_dist(r4.x, g4.x, b4.x);
        acc += pix_dist(r4.y, g4.y, b4.y);
        acc += pix_dist(r4.z, g4.z, b4.z);
        acc += pix_dist(r4.w, g4.w, b4.w);
    }

    // warp reduction
    #pragma unroll
    for (int sh = 16; sh > 0; sh >>= 1)
        acc += __shfl_xor_sync(0xFFFFFFFFu, acc, sh);

    __shared__ float warp_sums[8];
    int lane = threadIdx.x & 31;
    int wid  = threadIdx.x >> 5;
    if (lane == 0) warp_sums[wid] = acc;
    __syncthreads();

    if (wid == 0) {
        float v = (lane < (blockDim.x >> 5)) ? warp_sums[lane] : 0.0f;
        #pragma unroll
        for (int sh = 4; sh > 0; sh >>= 1)
            v += __shfl_xor_sync(0xFFFFFFFFu, v, sh);
        if (lane == 0) atomicAdd(out, v * inv_n);
    }
}

extern "C" void kernel_launch(void* const* d_in, const int* in_sizes, int n_in,
                              void* d_out, int out_size)
{
    const float* x = (const float*)d_in[0];
    float* out = (float*)d_out;

    int n_elems  = in_sizes[0];          // B*3*H*W
    int n_pixels = n_elems / 3;          // B*H*W = 8388608
    int n_groups = n_pixels >> 2;        // 4 pixels per group
    float inv_n  = 1.0f / (float)n_pixels;

    nps_zero_kernel<<<1, 32>>>(out);

    const int threads = 256;
    int blocks = (n_groups + threads - 1) / threads;
    const int max_blocks = 148 * 16;     // persistent-ish grid-stride
    if (blocks > max_blocks) blocks = max_blocks;
    nps_loss_kernel<<<blocks, threads>>>(x, out, n_groups, inv_n);
}

// round 3
// speedup vs baseline: 1.3172x; 1.3172x over previous
#include <cuda_runtime.h>
#include <math.h>

// NPSLoss: mean over pixels of sqrt(min_k ||p - c_k||^2), 20-color fixed codebook.
// d2_k = |p|^2 + s_k,  s_k = |c_k|^2 - 2 p.c_k.
// All non-black s_k are DECREASING affine functions of one of:
//   vmax = max(r,g,b)          (9 single-channel colors -> 3 lines)
//   smax = rgb - min(r,g,b)    (6 two-channel colors    -> 2 lines)
//   rgb  = r+g+b               (4 gray colors           -> 4 lines)
// Black (0,0,0) gives s=0 -> d2 candidate = |p|^2.

#define HW_SHIFT 18            // 512*512
#define HW (1 << HW_SHIFT)

struct f8 { float v[8]; };

__device__ __forceinline__ f8 ldg_el8(const float* p) {
    unsigned a0, a1, a2, a3, a4, a5, a6, a7;
    asm("ld.global.nc.L2::evict_last.v8.b32 {%0,%1,%2,%3,%4,%5,%6,%7}, [%8];"
        : "=r"(a0), "=r"(a1), "=r"(a2), "=r"(a3),
          "=r"(a4), "=r"(a5), "=r"(a6), "=r"(a7)
        : "l"(p));
    f8 o;
    o.v[0] = __uint_as_float(a0); o.v[1] = __uint_as_float(a1);
    o.v[2] = __uint_as_float(a2); o.v[3] = __uint_as_float(a3);
    o.v[4] = __uint_as_float(a4); o.v[5] = __uint_as_float(a5);
    o.v[6] = __uint_as_float(a6); o.v[7] = __uint_as_float(a7);
    return o;
}

__device__ __forceinline__ float pix_dist(float r, float g, float b) {
    float rgb  = (r + g) + b;
    float vmax = fmaxf(fmaxf(r, g), b);
    float vmin = fminf(fminf(r, g), b);
    float smax = rgb - vmin;                       // max of the pair sums
    float pp   = fmaf(r, r, fmaf(g, g, b * b));

    // single-channel colors c in {0.5, 0.75, 1}, evaluated at vmax
    float m1 = fminf(0.25f - vmax, fmaf(-1.5f, vmax, 0.5625f));
    m1 = fminf(m1, fmaf(-2.0f, vmax, 1.0f));
    // pair colors c in {0.5, 1}, evaluated at smax
    float m2 = fminf(0.5f - smax, fmaf(-2.0f, smax, 2.0f));
    // grays c in {0.25, 0.5, 0.75, 1}, evaluated at rgb
    float m3 = fminf(fmaf(-0.5f, rgb, 0.1875f), 0.75f - rgb);
    m3 = fminf(m3, fminf(fmaf(-1.5f, rgb, 1.6875f), fmaf(-2.0f, rgb, 3.0f)));

    float m  = fminf(fminf(m1, m2), m3);
    float d2 = fminf(pp + m, pp);                  // black color: s = 0
    float y;
    asm("sqrt.approx.f32 %0, %1;" : "=f"(y) : "f"(fabsf(d2)));
    return y;
}

__global__ void nps_zero_kernel(float* out) {
    if (threadIdx.x == 0 && blockIdx.x == 0) out[0] = 0.0f;
}

__global__ void __launch_bounds__(256) nps_loss_kernel(
    const float* __restrict__ x, float* __restrict__ out,
    int n_pairs, float inv_n)
{
    float acc = 0.0f;
    const int stride = gridDim.x * blockDim.x;
    for (int pi = blockIdx.x * blockDim.x + threadIdx.x; pi < n_pairs; pi += stride) {
        int p   = pi << 3;                 // 8 pixels per iteration
        int img = p >> HW_SHIFT;
        int off = p & (HW - 1);
        const float* base = x + (size_t)img * (3 * HW) + off;
        // 3 front-batched 32B loads -> high MLP, low issue pressure
        f8 r = ldg_el8(base);
        f8 g = ldg_el8(base + HW);
        f8 b = ldg_el8(base + 2 * HW);

        #pragma unroll
        for (int i = 0; i < 8; i++)
            acc += pix_dist(r.v[i], g.v[i], b.v[i]);
    }

    // warp reduction
    #pragma unroll
    for (int sh = 16; sh > 0; sh >>= 1)
        acc += __shfl_xor_sync(0xFFFFFFFFu, acc, sh);

    __shared__ float warp_sums[8];
    int lane = threadIdx.x & 31;
    int wid  = threadIdx.x >> 5;
    if (lane == 0) warp_sums[wid] = acc;
    __syncthreads();

    if (wid == 0) {
        float v = (lane < (blockDim.x >> 5)) ? warp_sums[lane] : 0.0f;
        #pragma unroll
        for (int sh = 4; sh > 0; sh >>= 1)
            v += __shfl_xor_sync(0xFFFFFFFFu, v, sh);
        if (lane == 0) atomicAdd(out, v * inv_n);
    }
}

extern "C" void kernel_launch(void* const* d_in, const int* in_sizes, int n_in,
                              void* d_out, int out_size)
{
    const float* x = (const float*)d_in[0];
    float* out = (float*)d_out;

    int n_elems  = in_sizes[0];          // B*3*H*W
    int n_pixels = n_elems / 3;          // 8388608
    int n_pairs  = n_pixels >> 3;        // 8 pixels per iteration
    float inv_n  = 1.0f / (float)n_pixels;

    nps_zero_kernel<<<1, 32>>>(out);

    const int threads = 256;
    int blocks = (n_pairs + threads - 1) / threads;
    const int max_blocks = 148 * 8;      // 1-wave persistent grid
    if (blocks > max_blocks) blocks = max_blocks;
    nps_loss_kernel<<<blocks, threads>>>(x, out, n_pairs, inv_n);
}